// round 6
// baseline (speedup 1.0000x reference)
#include <cuda_runtime.h>
#include <cuda_bf16.h>
#include <cstdint>
#include <cstddef>

#define BATCH 64
#define HW    256
#define CH    1024
#define NTOK  256
#define TC    768
#define FD    512
#define MROWS (BATCH*HW)   // 16384

// ------------------------------ scratch (device globals; no allocs) ---------
__device__ __align__(256) __nv_bfloat16 g_x1h[(size_t)MROWS*CH], g_x1l[(size_t)MROWS*CH];
__device__ __align__(256) __nv_bfloat16 g_x2h[(size_t)MROWS*TC], g_x2l[(size_t)MROWS*TC];
__device__ __align__(256) __nv_bfloat16 g_wqh[(size_t)FD*CH],  g_wql[(size_t)FD*CH];
__device__ __align__(256) __nv_bfloat16 g_wkh[(size_t)FD*TC],  g_wkl[(size_t)FD*TC];
__device__ __align__(256) __nv_bfloat16 g_wvh[(size_t)CH*TC],  g_wvl[(size_t)CH*TC];
__device__ __align__(256) __nv_bfloat16 g_woh[(size_t)CH*CH],  g_wol[(size_t)CH*CH];
__device__ __align__(256) __nv_bfloat16 g_Qh[(size_t)MROWS*FD], g_Ql[(size_t)MROWS*FD];
__device__ __align__(256) __nv_bfloat16 g_Kh[(size_t)MROWS*FD], g_Kl[(size_t)MROWS*FD];
__device__ __align__(256) float         g_V [(size_t)MROWS*CH];
__device__ __align__(256) __nv_bfloat16 g_Vth[(size_t)MROWS*CH], g_Vtl[(size_t)MROWS*CH]; // [b][CH][NTOK]
__device__ __align__(256) float         g_S [(size_t)MROWS*NTOK];
__device__ __align__(256) __nv_bfloat16 g_bh[(size_t)MROWS*NTOK], g_bl[(size_t)MROWS*NTOK];
__device__ __align__(256) __nv_bfloat16 g_O1h[(size_t)MROWS*CH], g_O1l[(size_t)MROWS*CH];

// ------------------------------ PTX helpers (all portable, sm_80+) ----------
__device__ __forceinline__ uint32_t smem_u32(const void* p) {
    uint32_t a;
    asm("{ .reg .u64 t; cvta.to.shared.u64 t, %1; cvt.u32.u64 %0, t; }" : "=r"(a) : "l"(p));
    return a;
}
#define CP_ASYNC16(dst, src) \
    asm volatile("cp.async.cg.shared.global [%0], [%1], 16;" :: "r"(dst), "l"(src))
#define CP_COMMIT() asm volatile("cp.async.commit_group;" ::: "memory")
#define CP_WAIT1()  asm volatile("cp.async.wait_group 1;" ::: "memory")
#define CP_WAIT0()  asm volatile("cp.async.wait_group 0;" ::: "memory")

#define LDMX4(r, addr)                                                      \
    asm volatile("ldmatrix.sync.aligned.m8n8.x4.shared.b16 {%0,%1,%2,%3}, [%4];" \
        : "=r"((r)[0]), "=r"((r)[1]), "=r"((r)[2]), "=r"((r)[3]) : "r"(addr))

#define MMA16816(c, a, b)                                                   \
    asm volatile("mma.sync.aligned.m16n8k16.row.col.f32.bf16.bf16.f32 "     \
        "{%0,%1,%2,%3}, {%4,%5,%6,%7}, {%8,%9}, {%0,%1,%2,%3};"             \
        : "+f"((c)[0]), "+f"((c)[1]), "+f"((c)[2]), "+f"((c)[3])            \
        : "r"((a)[0]), "r"((a)[1]), "r"((a)[2]), "r"((a)[3]),               \
          "r"((b)[0]), "r"((b)[1]))

// ------------------------------ GEMM ----------------------------------------
// C[M,N] (+bias) = (Ah+Al)[M,K] * (Bh+Bl)[N,K]^T via 3 bf16 MMAs (AhBh+AhBl+AlBh).
// CTA tile 128x128, K-slab 64, 8 warps (each 32x64), cp.async double buffer.
// MMAs ordered by TERM (hh x4, hl x4, lh x4) so consecutive instructions hit
// distinct accumulators: RAW reuse distance 4 instead of 1.
// Requires M,N % 128 == 0, K % 64 == 0.
// MODE 0: fp32 C.  MODE 1: bf16 hi/lo split C.

#define STG_BYTES 65536   // 4 matrices x 16KB (128 rows x 128B swizzled)
#define SMEM_BYTES (2*STG_BYTES)

// copy one 128x64 bf16 tile into swizzled smem via cp.async (1024 x 16B)
__device__ __forceinline__ void cp_tile(
    const __nv_bfloat16* __restrict__ g, int row0, int kof, int pitch,
    uint32_t sdst, int tid)
{
#pragma unroll
    for (int i = 0; i < 4; ++i) {
        int u = tid + i * 256;
        int row = u >> 3;
        int c = u & 7;
        uint32_t dst = sdst + row * 128 + ((c ^ (row & 7)) << 4);
        const void* src = g + (size_t)(row0 + row) * pitch + kof + c * 8;
        CP_ASYNC16(dst, src);
    }
}

template <int MODE>
__global__ __launch_bounds__(256, 1) void mma_gemm(
    const __nv_bfloat16* __restrict__ Ah, const __nv_bfloat16* __restrict__ Al,
    const __nv_bfloat16* __restrict__ Bh, const __nv_bfloat16* __restrict__ Bl,
    const float* __restrict__ bias,
    float* __restrict__ Cf, __nv_bfloat16* __restrict__ Chi, __nv_bfloat16* __restrict__ Clo,
    int K, int ldc, size_t sA, size_t sB, size_t sC)
{
    extern __shared__ char smem[];
    const uint32_t sbase = smem_u32(smem);
    const int tid  = threadIdx.x;
    const int lane = tid & 31;
    const int wid  = tid >> 5;
    const int mw   = wid & 3;    // 4 warps along M
    const int nw   = wid >> 2;   // 2 warps along N
    const int m0 = blockIdx.y * 128;
    const int n0 = blockIdx.x * 128;
    const size_t z = blockIdx.z;
    Ah += z * sA; Al += z * sA;
    Bh += z * sB; Bl += z * sB;

    float c[2][8][4];
#pragma unroll
    for (int i = 0; i < 2; ++i)
#pragma unroll
        for (int j = 0; j < 8; ++j)
#pragma unroll
            for (int e = 0; e < 4; ++e) c[i][j][e] = 0.f;

    const int KS = K >> 6;

    // prologue: slab 0 -> stage 0
    cp_tile(Ah, m0, 0, K, sbase + 0,     tid);
    cp_tile(Al, m0, 0, K, sbase + 16384, tid);
    cp_tile(Bh, n0, 0, K, sbase + 32768, tid);
    cp_tile(Bl, n0, 0, K, sbase + 49152, tid);
    CP_COMMIT();

    // precomputed ldmatrix lane offsets
    const int a_r = lane & 15;          // row within 16-row A tile
    const int a_c = lane >> 4;          // k-chunk select (0/1)
    const int b_r = ((lane >> 4) << 3) + (lane & 7);   // row within 16-row B pair
    const int b_c = (lane >> 3) & 1;    // k-chunk select

    for (int s = 0; s < KS; ++s) {
        const uint32_t sb = sbase + (s & 1) * STG_BYTES;
        if (s + 1 < KS) {
            const uint32_t nb = sbase + ((s + 1) & 1) * STG_BYTES;
            const int kof = (s + 1) * 64;
            cp_tile(Ah, m0, kof, K, nb + 0,     tid);
            cp_tile(Al, m0, kof, K, nb + 16384, tid);
            cp_tile(Bh, n0, kof, K, nb + 32768, tid);
            cp_tile(Bl, n0, kof, K, nb + 49152, tid);
            CP_COMMIT();
            CP_WAIT1();
        } else {
            CP_WAIT0();
        }
        __syncthreads();

#pragma unroll
        for (int kk = 0; kk < 4; ++kk) {
            uint32_t a_h[2][4], a_l[2][4];
#pragma unroll
            for (int mi = 0; mi < 2; ++mi) {
                const int row = mw * 32 + mi * 16 + a_r;
                const int ch = kk * 2 + a_c;
                const uint32_t ad = sb + row * 128 + ((ch ^ (row & 7)) << 4);
                LDMX4(a_h[mi], ad);
                LDMX4(a_l[mi], ad + 16384);
            }
#pragma unroll
            for (int np = 0; np < 4; ++np) {
                const int n = nw * 64 + np * 16 + b_r;
                const int ch = kk * 2 + b_c;
                const uint32_t bd = sb + 32768 + n * 128 + ((ch ^ (n & 7)) << 4);
                uint32_t bhf[4], blf[4];
                LDMX4(bhf, bd);
                LDMX4(blf, bd + 16384);
                // term-ordered: 4 independent accumulators between reuses
                // hh
                MMA16816(c[0][2*np+0], a_h[0], &bhf[0]);
                MMA16816(c[0][2*np+1], a_h[0], &bhf[2]);
                MMA16816(c[1][2*np+0], a_h[1], &bhf[0]);
                MMA16816(c[1][2*np+1], a_h[1], &bhf[2]);
                // hl
                MMA16816(c[0][2*np+0], a_h[0], &blf[0]);
                MMA16816(c[0][2*np+1], a_h[0], &blf[2]);
                MMA16816(c[1][2*np+0], a_h[1], &blf[0]);
                MMA16816(c[1][2*np+1], a_h[1], &blf[2]);
                // lh
                MMA16816(c[0][2*np+0], a_l[0], &bhf[0]);
                MMA16816(c[0][2*np+1], a_l[0], &bhf[2]);
                MMA16816(c[1][2*np+0], a_l[1], &bhf[0]);
                MMA16816(c[1][2*np+1], a_l[1], &bhf[2]);
            }
        }
        __syncthreads();
    }

    // ---- epilogue ----
    const int r_base = m0 + mw * 32 + (lane >> 2);
    const int c_base = n0 + nw * 64 + (lane & 3) * 2;
#pragma unroll
    for (int mi = 0; mi < 2; ++mi) {
#pragma unroll
        for (int hf = 0; hf < 2; ++hf) {
            const size_t row = (size_t)(r_base + mi * 16 + hf * 8);
#pragma unroll
            for (int nj = 0; nj < 8; ++nj) {
                const int col = c_base + nj * 8;
                float v0 = c[mi][nj][hf * 2 + 0];
                float v1 = c[mi][nj][hf * 2 + 1];
                if (bias) { v0 += __ldg(&bias[col]); v1 += __ldg(&bias[col + 1]); }
                if (MODE == 0) {
                    float2* dst = (float2*)(Cf + z * sC + row * ldc + col);
                    *dst = make_float2(v0, v1);
                } else {
                    __nv_bfloat16 h0 = __float2bfloat16_rn(v0);
                    __nv_bfloat16 h1 = __float2bfloat16_rn(v1);
                    __nv_bfloat16 l0 = __float2bfloat16_rn(v0 - __bfloat162float(h0));
                    __nv_bfloat16 l1 = __float2bfloat16_rn(v1 - __bfloat162float(h1));
                    uint32_t hw = (uint32_t)__bfloat16_as_ushort(h0) | ((uint32_t)__bfloat16_as_ushort(h1) << 16);
                    uint32_t lw = (uint32_t)__bfloat16_as_ushort(l0) | ((uint32_t)__bfloat16_as_ushort(l1) << 16);
                    *(uint32_t*)(Chi + z * sC + row * ldc + col) = hw;
                    *(uint32_t*)(Clo + z * sC + row * ldc + col) = lw;
                }
            }
        }
    }
}

// ------------------------------ aux kernels ---------------------------------
__global__ __launch_bounds__(256) void split_kernel(
    const float4* __restrict__ src, __nv_bfloat16* __restrict__ dh,
    __nv_bfloat16* __restrict__ dl, int n4)
{
    int i = blockIdx.x * 256 + threadIdx.x;
    if (i >= n4) return;
    float4 v = src[i];
    float fv[4] = {v.x, v.y, v.z, v.w};
    uint32_t hw[2], lw[2];
#pragma unroll
    for (int p = 0; p < 2; ++p) {
        __nv_bfloat16 h0 = __float2bfloat16_rn(fv[2*p]);
        __nv_bfloat16 h1 = __float2bfloat16_rn(fv[2*p+1]);
        __nv_bfloat16 l0 = __float2bfloat16_rn(fv[2*p]   - __bfloat162float(h0));
        __nv_bfloat16 l1 = __float2bfloat16_rn(fv[2*p+1] - __bfloat162float(h1));
        hw[p] = (uint32_t)__bfloat16_as_ushort(h0) | ((uint32_t)__bfloat16_as_ushort(h1) << 16);
        lw[p] = (uint32_t)__bfloat16_as_ushort(l0) | ((uint32_t)__bfloat16_as_ushort(l1) << 16);
    }
    ((uint2*)dh)[i] = make_uint2(hw[0], hw[1]);
    ((uint2*)dl)[i] = make_uint2(lw[0], lw[1]);
}

// dst[c][r] = split(src[r][c]); src [R,C] fp32, dst [C,R] bf16 hi/lo, batched.
__global__ __launch_bounds__(256) void tsplit_kernel(
    const float* __restrict__ src, __nv_bfloat16* __restrict__ dh,
    __nv_bfloat16* __restrict__ dl, int R, int C, size_t sS, size_t sD)
{
    __shared__ float t[32][33];
    const size_t z = blockIdx.z;
    src += z * sS; dh += z * sD; dl += z * sD;
    const int c0 = blockIdx.x * 32, r0 = blockIdx.y * 32;
    const int tx = threadIdx.x, ty = threadIdx.y;
#pragma unroll
    for (int k = 0; k < 4; ++k)
        t[ty + 8*k][tx] = src[(size_t)(r0 + ty + 8*k) * C + c0 + tx];
    __syncthreads();
#pragma unroll
    for (int k = 0; k < 4; ++k) {
        float f = t[tx][ty + 8*k];
        __nv_bfloat16 h = __float2bfloat16_rn(f);
        size_t o = (size_t)(c0 + ty + 8*k) * R + r0 + tx;
        dh[o] = h;
        dl[o] = __float2bfloat16_rn(f - __bfloat162float(h));
    }
}

__global__ __launch_bounds__(256) void softmax_mask_split_kernel(
    const float* __restrict__ S, const float* __restrict__ masks,
    float* __restrict__ beta, __nv_bfloat16* __restrict__ bh,
    __nv_bfloat16* __restrict__ bl)
{
    const int row = blockIdx.x;
    const int b = row >> 8;
    const int n = threadIdx.x;
    __shared__ float red[256];

    const size_t idx = (size_t)row * NTOK + n;
    float v = S[idx];
    red[n] = v;
    __syncthreads();
#pragma unroll
    for (int s = 128; s > 0; s >>= 1) {
        if (n < s) red[n] = fmaxf(red[n], red[n + s]);
        __syncthreads();
    }
    const float mx = red[0];
    __syncthreads();
    const float e = expf(v - mx);
    red[n] = e;
    __syncthreads();
#pragma unroll
    for (int s = 128; s > 0; s >>= 1) {
        if (n < s) red[n] += red[n + s];
        __syncthreads();
    }
    const float r = e / red[0] * masks[b * NTOK + n];
    beta[idx] = r;
    __nv_bfloat16 h = __float2bfloat16_rn(r);
    bh[idx] = h;
    bl[idx] = __float2bfloat16_rn(r - __bfloat162float(h));
}

// ------------------------------ host ----------------------------------------
extern "C" void kernel_launch(void* const* d_in, const int* in_sizes, int n_in,
                              void* d_out, int out_size) {
    const float* x1    = (const float*)d_in[0];
    const float* x2    = (const float*)d_in[1];
    const float* masks = (const float*)d_in[2];
    const float* wq    = (const float*)d_in[3];
    const float* bq    = (const float*)d_in[4];
    const float* wk    = (const float*)d_in[5];
    const float* bk    = (const float*)d_in[6];
    const float* wv    = (const float*)d_in[7];
    const float* bv    = (const float*)d_in[8];
    const float* wo    = (const float*)d_in[9];
    const float* bo    = (const float*)d_in[10];

    float* out      = (float*)d_out;
    float* o_out    = out;
    float* beta_out = out + (size_t)MROWS * CH;

    __nv_bfloat16 *x1h, *x1l, *x2h, *x2l, *wqh, *wql, *wkh, *wkl, *wvh, *wvl,
                  *woh, *wol, *Qh, *Ql, *Kh, *Kl, *Vth, *Vtl, *bh, *bl, *O1h, *O1l;
    float *Vf, *Sf;
    cudaGetSymbolAddress((void**)&x1h, g_x1h); cudaGetSymbolAddress((void**)&x1l, g_x1l);
    cudaGetSymbolAddress((void**)&x2h, g_x2h); cudaGetSymbolAddress((void**)&x2l, g_x2l);
    cudaGetSymbolAddress((void**)&wqh, g_wqh); cudaGetSymbolAddress((void**)&wql, g_wql);
    cudaGetSymbolAddress((void**)&wkh, g_wkh); cudaGetSymbolAddress((void**)&wkl, g_wkl);
    cudaGetSymbolAddress((void**)&wvh, g_wvh); cudaGetSymbolAddress((void**)&wvl, g_wvl);
    cudaGetSymbolAddress((void**)&woh, g_woh); cudaGetSymbolAddress((void**)&wol, g_wol);
    cudaGetSymbolAddress((void**)&Qh,  g_Qh);  cudaGetSymbolAddress((void**)&Ql,  g_Ql);
    cudaGetSymbolAddress((void**)&Kh,  g_Kh);  cudaGetSymbolAddress((void**)&Kl,  g_Kl);
    cudaGetSymbolAddress((void**)&Vf,  g_V);
    cudaGetSymbolAddress((void**)&Vth, g_Vth); cudaGetSymbolAddress((void**)&Vtl, g_Vtl);
    cudaGetSymbolAddress((void**)&Sf,  g_S);
    cudaGetSymbolAddress((void**)&bh,  g_bh);  cudaGetSymbolAddress((void**)&bl,  g_bl);
    cudaGetSymbolAddress((void**)&O1h, g_O1h); cudaGetSymbolAddress((void**)&O1l, g_O1l);

    cudaFuncSetAttribute(mma_gemm<0>, cudaFuncAttributeMaxDynamicSharedMemorySize, SMEM_BYTES);
    cudaFuncSetAttribute(mma_gemm<1>, cudaFuncAttributeMaxDynamicSharedMemorySize, SMEM_BYTES);

    const dim3 T(256);
    const dim3 TT(32, 8);

    // split activations
    {
        int n4 = MROWS * CH / 4;
        split_kernel<<<(n4 + 255) / 256, 256>>>((const float4*)x1, x1h, x1l, n4);
    }
    {
        int n4 = MROWS * TC / 4;
        split_kernel<<<(n4 + 255) / 256, 256>>>((const float4*)x2, x2h, x2l, n4);
    }
    // transpose+split weights:  W[K,N] -> Wt[N,K]
    tsplit_kernel<<<dim3(FD/32, CH/32, 1), TT>>>(wq, wqh, wql, CH, FD, 0, 0);
    tsplit_kernel<<<dim3(FD/32, TC/32, 1), TT>>>(wk, wkh, wkl, TC, FD, 0, 0);
    tsplit_kernel<<<dim3(CH/32, TC/32, 1), TT>>>(wv, wvh, wvl, TC, CH, 0, 0);
    tsplit_kernel<<<dim3(CH/32, CH/32, 1), TT>>>(wo, woh, wol, CH, CH, 0, 0);

    // Q = x1 @ Wq + bq  -> hi/lo
    mma_gemm<1><<<dim3(FD/128, MROWS/128, 1), T, SMEM_BYTES>>>(
        x1h, x1l, wqh, wql, bq, nullptr, Qh, Ql, CH, FD, 0, 0, 0);
    // K = x2 @ Wk + bk  -> hi/lo
    mma_gemm<1><<<dim3(FD/128, MROWS/128, 1), T, SMEM_BYTES>>>(
        x2h, x2l, wkh, wkl, bk, nullptr, Kh, Kl, TC, FD, 0, 0, 0);
    // V = x2 @ Wv + bv  -> fp32, then transpose+split per batch
    mma_gemm<0><<<dim3(CH/128, MROWS/128, 1), T, SMEM_BYTES>>>(
        x2h, x2l, wvh, wvl, bv, Vf, nullptr, nullptr, TC, CH, 0, 0, 0);
    tsplit_kernel<<<dim3(CH/32, NTOK/32, BATCH), TT>>>(
        Vf, Vth, Vtl, NTOK, CH, (size_t)NTOK*CH, (size_t)NTOK*CH);

    // S[b] = Q_b @ K_b^T -> fp32
    mma_gemm<0><<<dim3(NTOK/128, HW/128, BATCH), T, SMEM_BYTES>>>(
        Qh, Ql, Kh, Kl, nullptr, Sf, nullptr, nullptr, FD, NTOK,
        (size_t)HW*FD, (size_t)NTOK*FD, (size_t)HW*NTOK);

    // beta = softmax(S) * mask -> d_out + hi/lo
    softmax_mask_split_kernel<<<MROWS, 256>>>(Sf, masks, beta_out, bh, bl);

    // O1[b] = beta_b @ V_b -> hi/lo   (B operand = Vt [CH, NTOK])
    mma_gemm<1><<<dim3(CH/128, HW/128, BATCH), T, SMEM_BYTES>>>(
        bh, bl, Vth, Vtl, nullptr, nullptr, O1h, O1l, NTOK, CH,
        (size_t)HW*NTOK, (size_t)CH*NTOK, (size_t)HW*CH);

    // o = O1 @ Wo + bo -> fp32 out
    mma_gemm<0><<<dim3(CH/128, MROWS/128, 1), T, SMEM_BYTES>>>(
        O1h, O1l, woh, wol, bo, o_out, nullptr, nullptr, CH, CH, 0, 0, 0);
}

// round 7
// speedup vs baseline: 1.5243x; 1.5243x over previous
#include <cuda_runtime.h>
#include <cuda_bf16.h>
#include <cstdint>
#include <cstddef>

#define BATCH 64
#define HW    256
#define CH    1024
#define NTOK  256
#define TC    768
#define FD    512
#define MROWS (BATCH*HW)   // 16384

// ------------------------------ scratch (device globals; no allocs) ---------
__device__ __align__(256) __nv_bfloat16 g_x1h[(size_t)MROWS*CH], g_x1l[(size_t)MROWS*CH];
__device__ __align__(256) __nv_bfloat16 g_x2h[(size_t)MROWS*TC], g_x2l[(size_t)MROWS*TC];
__device__ __align__(256) __nv_bfloat16 g_wqh[(size_t)FD*CH],  g_wql[(size_t)FD*CH];
__device__ __align__(256) __nv_bfloat16 g_wkh[(size_t)FD*TC],  g_wkl[(size_t)FD*TC];
__device__ __align__(256) __nv_bfloat16 g_wvh[(size_t)CH*TC],  g_wvl[(size_t)CH*TC];
__device__ __align__(256) __nv_bfloat16 g_woh[(size_t)CH*CH],  g_wol[(size_t)CH*CH];
__device__ __align__(256) __nv_bfloat16 g_Qh[(size_t)MROWS*FD], g_Ql[(size_t)MROWS*FD];
__device__ __align__(256) __nv_bfloat16 g_Kh[(size_t)MROWS*FD], g_Kl[(size_t)MROWS*FD];
__device__ __align__(256) float         g_V [(size_t)MROWS*CH];
__device__ __align__(256) __nv_bfloat16 g_Vth[(size_t)MROWS*CH], g_Vtl[(size_t)MROWS*CH]; // [b][CH][NTOK]
__device__ __align__(256) float         g_S [(size_t)MROWS*NTOK];
__device__ __align__(256) __nv_bfloat16 g_bh[(size_t)MROWS*NTOK], g_bl[(size_t)MROWS*NTOK];
__device__ __align__(256) __nv_bfloat16 g_O1h[(size_t)MROWS*CH], g_O1l[(size_t)MROWS*CH];

// ------------------------------ PTX helpers (all portable, sm_80+) ----------
__device__ __forceinline__ uint32_t smem_u32(const void* p) {
    uint32_t a;
    asm("{ .reg .u64 t; cvta.to.shared.u64 t, %1; cvt.u32.u64 %0, t; }" : "=r"(a) : "l"(p));
    return a;
}
#define CP_ASYNC16(dst, src) \
    asm volatile("cp.async.cg.shared.global [%0], [%1], 16;" :: "r"(dst), "l"(src))
#define CP_COMMIT() asm volatile("cp.async.commit_group;" ::: "memory")
#define CP_WAIT1()  asm volatile("cp.async.wait_group 1;" ::: "memory")
#define CP_WAIT0()  asm volatile("cp.async.wait_group 0;" ::: "memory")

#define LDMX4(r, addr)                                                      \
    asm volatile("ldmatrix.sync.aligned.m8n8.x4.shared.b16 {%0,%1,%2,%3}, [%4];" \
        : "=r"((r)[0]), "=r"((r)[1]), "=r"((r)[2]), "=r"((r)[3]) : "r"(addr))

#define MMA16816(c, a, b)                                                   \
    asm volatile("mma.sync.aligned.m16n8k16.row.col.f32.bf16.bf16.f32 "     \
        "{%0,%1,%2,%3}, {%4,%5,%6,%7}, {%8,%9}, {%0,%1,%2,%3};"             \
        : "+f"((c)[0]), "+f"((c)[1]), "+f"((c)[2]), "+f"((c)[3])            \
        : "r"((a)[0]), "r"((a)[1]), "r"((a)[2]), "r"((a)[3]),               \
          "r"((b)[0]), "r"((b)[1]))

// ------------------------------ GEMM ----------------------------------------
// C[M,N] (+bias) = (Ah+Al)[M,K] * (Bh+Bl)[N,K]^T via 3 bf16 MMAs (AhBh+AhBl+AlBh),
// R4 accumulator ordering (fastest measured).
// CTA tile 128x128, K-slab 32, 8 warps, cp.async double buffer, 64KB smem
// => 2 CTAs/SM for latency hiding.
// SMEM row layout (128B/row, XOR-swizzled 16B chunks): chunks 0-3 = hi k-data,
// chunks 4-7 = lo k-data of the same 32-wide k slab.
// Requires M,N % 128 == 0, K % 32 == 0.
// MODE 0: fp32 C.  MODE 1: bf16 hi/lo split C.

#define STG_BYTES 32768   // A tile 16KB + B tile 16KB
#define SMEM_BYTES (2*STG_BYTES)

// copy one 128x32 hi+lo tile pair into combined swizzled smem (1024 x 16B)
__device__ __forceinline__ void cp_tile2(
    const __nv_bfloat16* __restrict__ gh, const __nv_bfloat16* __restrict__ gl,
    int row0, int kof, int pitch, uint32_t sdst, int tid)
{
#pragma unroll
    for (int i = 0; i < 2; ++i) {
        int u = tid + i * 256;          // 0..511, covers A or B half (2 iters x 256 thr)
        int row = u >> 2;               // 0..127
        int c4 = u & 3;                 // hi chunk 0..3
        // hi chunk
        {
            int c = c4;
            uint32_t dst = sdst + row * 128 + ((c ^ (row & 7)) << 4);
            const void* src = gh + (size_t)(row0 + row) * pitch + kof + c4 * 8;
            CP_ASYNC16(dst, src);
        }
        // lo chunk
        {
            int c = c4 + 4;
            uint32_t dst = sdst + row * 128 + ((c ^ (row & 7)) << 4);
            const void* src = gl + (size_t)(row0 + row) * pitch + kof + c4 * 8;
            CP_ASYNC16(dst, src);
        }
    }
}

template <int MODE>
__global__ __launch_bounds__(256, 2) void mma_gemm(
    const __nv_bfloat16* __restrict__ Ah, const __nv_bfloat16* __restrict__ Al,
    const __nv_bfloat16* __restrict__ Bh, const __nv_bfloat16* __restrict__ Bl,
    const float* __restrict__ bias,
    float* __restrict__ Cf, __nv_bfloat16* __restrict__ Chi, __nv_bfloat16* __restrict__ Clo,
    int K, int ldc, size_t sA, size_t sB, size_t sC)
{
    extern __shared__ char smem[];
    const uint32_t sbase = smem_u32(smem);
    const int tid  = threadIdx.x;
    const int lane = tid & 31;
    const int wid  = tid >> 5;
    const int mw   = wid & 3;    // 4 warps along M
    const int nw   = wid >> 2;   // 2 warps along N
    const int m0 = blockIdx.y * 128;
    const int n0 = blockIdx.x * 128;
    const size_t z = blockIdx.z;
    Ah += z * sA; Al += z * sA;
    Bh += z * sB; Bl += z * sB;

    float c[2][8][4];
#pragma unroll
    for (int i = 0; i < 2; ++i)
#pragma unroll
        for (int j = 0; j < 8; ++j)
#pragma unroll
            for (int e = 0; e < 4; ++e) c[i][j][e] = 0.f;

    const int KS = K >> 5;       // 32-wide slabs

    // prologue: slab 0 -> stage 0
    cp_tile2(Ah, Al, m0, 0, K, sbase + 0,     tid);
    cp_tile2(Bh, Bl, n0, 0, K, sbase + 16384, tid);
    CP_COMMIT();

    // ldmatrix lane offsets
    const int a_r = lane & 15;
    const int a_c = lane >> 4;                          // 0/1
    const int b_r = ((lane >> 4) << 3) + (lane & 7);
    const int b_c = (lane >> 3) & 1;                    // 0/1

    for (int s = 0; s < KS; ++s) {
        const uint32_t sb = sbase + (s & 1) * STG_BYTES;
        if (s + 1 < KS) {
            const uint32_t nb = sbase + ((s + 1) & 1) * STG_BYTES;
            const int kof = (s + 1) * 32;
            cp_tile2(Ah, Al, m0, kof, K, nb + 0,     tid);
            cp_tile2(Bh, Bl, n0, kof, K, nb + 16384, tid);
            CP_COMMIT();
            CP_WAIT1();
        } else {
            CP_WAIT0();
        }
        __syncthreads();

#pragma unroll
        for (int kk = 0; kk < 2; ++kk) {
            uint32_t a_h[2][4], a_l[2][4];
#pragma unroll
            for (int mi = 0; mi < 2; ++mi) {
                const int row = mw * 32 + mi * 16 + a_r;
                const int ch = kk * 2 + a_c;            // hi chunk 0..3
                const uint32_t base = sb + row * 128;
                LDMX4(a_h[mi], base + ((ch       ^ (row & 7)) << 4));
                LDMX4(a_l[mi], base + (((ch + 4) ^ (row & 7)) << 4));
            }
#pragma unroll
            for (int np = 0; np < 4; ++np) {
                const int n = nw * 64 + np * 16 + b_r;
                const int ch = kk * 2 + b_c;
                const uint32_t base = sb + 16384 + n * 128;
                uint32_t bhf[4], blf[4];
                LDMX4(bhf, base + ((ch       ^ (n & 7)) << 4));
                LDMX4(blf, base + (((ch + 4) ^ (n & 7)) << 4));
                // R4 ordering: group by accumulator
#pragma unroll
                for (int mi = 0; mi < 2; ++mi) {
                    MMA16816(c[mi][2*np+0], a_h[mi], &bhf[0]);
                    MMA16816(c[mi][2*np+0], a_h[mi], &blf[0]);
                    MMA16816(c[mi][2*np+0], a_l[mi], &bhf[0]);
                    MMA16816(c[mi][2*np+1], a_h[mi], &bhf[2]);
                    MMA16816(c[mi][2*np+1], a_h[mi], &blf[2]);
                    MMA16816(c[mi][2*np+1], a_l[mi], &bhf[2]);
                }
            }
        }
        __syncthreads();
    }

    // ---- epilogue ----
    const int r_base = m0 + mw * 32 + (lane >> 2);
    const int c_base = n0 + nw * 64 + (lane & 3) * 2;
#pragma unroll
    for (int mi = 0; mi < 2; ++mi) {
#pragma unroll
        for (int hf = 0; hf < 2; ++hf) {
            const size_t row = (size_t)(r_base + mi * 16 + hf * 8);
#pragma unroll
            for (int nj = 0; nj < 8; ++nj) {
                const int col = c_base + nj * 8;
                float v0 = c[mi][nj][hf * 2 + 0];
                float v1 = c[mi][nj][hf * 2 + 1];
                if (bias) { v0 += __ldg(&bias[col]); v1 += __ldg(&bias[col + 1]); }
                if (MODE == 0) {
                    float2* dst = (float2*)(Cf + z * sC + row * ldc + col);
                    *dst = make_float2(v0, v1);
                } else {
                    __nv_bfloat16 h0 = __float2bfloat16_rn(v0);
                    __nv_bfloat16 h1 = __float2bfloat16_rn(v1);
                    __nv_bfloat16 l0 = __float2bfloat16_rn(v0 - __bfloat162float(h0));
                    __nv_bfloat16 l1 = __float2bfloat16_rn(v1 - __bfloat162float(h1));
                    uint32_t hw = (uint32_t)__bfloat16_as_ushort(h0) | ((uint32_t)__bfloat16_as_ushort(h1) << 16);
                    uint32_t lw = (uint32_t)__bfloat16_as_ushort(l0) | ((uint32_t)__bfloat16_as_ushort(l1) << 16);
                    *(uint32_t*)(Chi + z * sC + row * ldc + col) = hw;
                    *(uint32_t*)(Clo + z * sC + row * ldc + col) = lw;
                }
            }
        }
    }
}

// ------------------------------ aux kernels ---------------------------------
__global__ __launch_bounds__(256) void split_kernel(
    const float4* __restrict__ src, __nv_bfloat16* __restrict__ dh,
    __nv_bfloat16* __restrict__ dl, int n4)
{
    int i = blockIdx.x * 256 + threadIdx.x;
    if (i >= n4) return;
    float4 v = src[i];
    float fv[4] = {v.x, v.y, v.z, v.w};
    uint32_t hw[2], lw[2];
#pragma unroll
    for (int p = 0; p < 2; ++p) {
        __nv_bfloat16 h0 = __float2bfloat16_rn(fv[2*p]);
        __nv_bfloat16 h1 = __float2bfloat16_rn(fv[2*p+1]);
        __nv_bfloat16 l0 = __float2bfloat16_rn(fv[2*p]   - __bfloat162float(h0));
        __nv_bfloat16 l1 = __float2bfloat16_rn(fv[2*p+1] - __bfloat162float(h1));
        hw[p] = (uint32_t)__bfloat16_as_ushort(h0) | ((uint32_t)__bfloat16_as_ushort(h1) << 16);
        lw[p] = (uint32_t)__bfloat16_as_ushort(l0) | ((uint32_t)__bfloat16_as_ushort(l1) << 16);
    }
    ((uint2*)dh)[i] = make_uint2(hw[0], hw[1]);
    ((uint2*)dl)[i] = make_uint2(lw[0], lw[1]);
}

// dst[c][r] = split(src[r][c]); src [R,C] fp32, dst [C,R] bf16 hi/lo, batched.
__global__ __launch_bounds__(256) void tsplit_kernel(
    const float* __restrict__ src, __nv_bfloat16* __restrict__ dh,
    __nv_bfloat16* __restrict__ dl, int R, int C, size_t sS, size_t sD)
{
    __shared__ float t[32][33];
    const size_t z = blockIdx.z;
    src += z * sS; dh += z * sD; dl += z * sD;
    const int c0 = blockIdx.x * 32, r0 = blockIdx.y * 32;
    const int tx = threadIdx.x, ty = threadIdx.y;
#pragma unroll
    for (int k = 0; k < 4; ++k)
        t[ty + 8*k][tx] = src[(size_t)(r0 + ty + 8*k) * C + c0 + tx];
    __syncthreads();
#pragma unroll
    for (int k = 0; k < 4; ++k) {
        float f = t[tx][ty + 8*k];
        __nv_bfloat16 h = __float2bfloat16_rn(f);
        size_t o = (size_t)(c0 + ty + 8*k) * R + r0 + tx;
        dh[o] = h;
        dl[o] = __float2bfloat16_rn(f - __bfloat162float(h));
    }
}

__global__ __launch_bounds__(256) void softmax_mask_split_kernel(
    const float* __restrict__ S, const float* __restrict__ masks,
    float* __restrict__ beta, __nv_bfloat16* __restrict__ bh,
    __nv_bfloat16* __restrict__ bl)
{
    const int row = blockIdx.x;
    const int b = row >> 8;
    const int n = threadIdx.x;
    __shared__ float red[256];

    const size_t idx = (size_t)row * NTOK + n;
    float v = S[idx];
    red[n] = v;
    __syncthreads();
#pragma unroll
    for (int s = 128; s > 0; s >>= 1) {
        if (n < s) red[n] = fmaxf(red[n], red[n + s]);
        __syncthreads();
    }
    const float mx = red[0];
    __syncthreads();
    const float e = expf(v - mx);
    red[n] = e;
    __syncthreads();
#pragma unroll
    for (int s = 128; s > 0; s >>= 1) {
        if (n < s) red[n] += red[n + s];
        __syncthreads();
    }
    const float r = e / red[0] * masks[b * NTOK + n];
    beta[idx] = r;
    __nv_bfloat16 h = __float2bfloat16_rn(r);
    bh[idx] = h;
    bl[idx] = __float2bfloat16_rn(r - __bfloat162float(h));
}

// ------------------------------ host ----------------------------------------
extern "C" void kernel_launch(void* const* d_in, const int* in_sizes, int n_in,
                              void* d_out, int out_size) {
    const float* x1    = (const float*)d_in[0];
    const float* x2    = (const float*)d_in[1];
    const float* masks = (const float*)d_in[2];
    const float* wq    = (const float*)d_in[3];
    const float* bq    = (const float*)d_in[4];
    const float* wk    = (const float*)d_in[5];
    const float* bk    = (const float*)d_in[6];
    const float* wv    = (const float*)d_in[7];
    const float* bv    = (const float*)d_in[8];
    const float* wo    = (const float*)d_in[9];
    const float* bo    = (const float*)d_in[10];

    float* out      = (float*)d_out;
    float* o_out    = out;
    float* beta_out = out + (size_t)MROWS * CH;

    __nv_bfloat16 *x1h, *x1l, *x2h, *x2l, *wqh, *wql, *wkh, *wkl, *wvh, *wvl,
                  *woh, *wol, *Qh, *Ql, *Kh, *Kl, *Vth, *Vtl, *bh, *bl, *O1h, *O1l;
    float *Vf, *Sf;
    cudaGetSymbolAddress((void**)&x1h, g_x1h); cudaGetSymbolAddress((void**)&x1l, g_x1l);
    cudaGetSymbolAddress((void**)&x2h, g_x2h); cudaGetSymbolAddress((void**)&x2l, g_x2l);
    cudaGetSymbolAddress((void**)&wqh, g_wqh); cudaGetSymbolAddress((void**)&wql, g_wql);
    cudaGetSymbolAddress((void**)&wkh, g_wkh); cudaGetSymbolAddress((void**)&wkl, g_wkl);
    cudaGetSymbolAddress((void**)&wvh, g_wvh); cudaGetSymbolAddress((void**)&wvl, g_wvl);
    cudaGetSymbolAddress((void**)&woh, g_woh); cudaGetSymbolAddress((void**)&wol, g_wol);
    cudaGetSymbolAddress((void**)&Qh,  g_Qh);  cudaGetSymbolAddress((void**)&Ql,  g_Ql);
    cudaGetSymbolAddress((void**)&Kh,  g_Kh);  cudaGetSymbolAddress((void**)&Kl,  g_Kl);
    cudaGetSymbolAddress((void**)&Vf,  g_V);
    cudaGetSymbolAddress((void**)&Vth, g_Vth); cudaGetSymbolAddress((void**)&Vtl, g_Vtl);
    cudaGetSymbolAddress((void**)&Sf,  g_S);
    cudaGetSymbolAddress((void**)&bh,  g_bh);  cudaGetSymbolAddress((void**)&bl,  g_bl);
    cudaGetSymbolAddress((void**)&O1h, g_O1h); cudaGetSymbolAddress((void**)&O1l, g_O1l);

    cudaFuncSetAttribute(mma_gemm<0>, cudaFuncAttributeMaxDynamicSharedMemorySize, SMEM_BYTES);
    cudaFuncSetAttribute(mma_gemm<1>, cudaFuncAttributeMaxDynamicSharedMemorySize, SMEM_BYTES);

    const dim3 T(256);
    const dim3 TT(32, 8);

    // split activations
    {
        int n4 = MROWS * CH / 4;
        split_kernel<<<(n4 + 255) / 256, 256>>>((const float4*)x1, x1h, x1l, n4);
    }
    {
        int n4 = MROWS * TC / 4;
        split_kernel<<<(n4 + 255) / 256, 256>>>((const float4*)x2, x2h, x2l, n4);
    }
    // transpose+split weights:  W[K,N] -> Wt[N,K]
    tsplit_kernel<<<dim3(FD/32, CH/32, 1), TT>>>(wq, wqh, wql, CH, FD, 0, 0);
    tsplit_kernel<<<dim3(FD/32, TC/32, 1), TT>>>(wk, wkh, wkl, TC, FD, 0, 0);
    tsplit_kernel<<<dim3(CH/32, TC/32, 1), TT>>>(wv, wvh, wvl, TC, CH, 0, 0);
    tsplit_kernel<<<dim3(CH/32, CH/32, 1), TT>>>(wo, woh, wol, CH, CH, 0, 0);

    // Q = x1 @ Wq + bq  -> hi/lo
    mma_gemm<1><<<dim3(FD/128, MROWS/128, 1), T, SMEM_BYTES>>>(
        x1h, x1l, wqh, wql, bq, nullptr, Qh, Ql, CH, FD, 0, 0, 0);
    // K = x2 @ Wk + bk  -> hi/lo
    mma_gemm<1><<<dim3(FD/128, MROWS/128, 1), T, SMEM_BYTES>>>(
        x2h, x2l, wkh, wkl, bk, nullptr, Kh, Kl, TC, FD, 0, 0, 0);
    // V = x2 @ Wv + bv  -> fp32, then transpose+split per batch
    mma_gemm<0><<<dim3(CH/128, MROWS/128, 1), T, SMEM_BYTES>>>(
        x2h, x2l, wvh, wvl, bv, Vf, nullptr, nullptr, TC, CH, 0, 0, 0);
    tsplit_kernel<<<dim3(CH/32, NTOK/32, BATCH), TT>>>(
        Vf, Vth, Vtl, NTOK, CH, (size_t)NTOK*CH, (size_t)NTOK*CH);

    // S[b] = Q_b @ K_b^T -> fp32
    mma_gemm<0><<<dim3(NTOK/128, HW/128, BATCH), T, SMEM_BYTES>>>(
        Qh, Ql, Kh, Kl, nullptr, Sf, nullptr, nullptr, FD, NTOK,
        (size_t)HW*FD, (size_t)NTOK*FD, (size_t)HW*NTOK);

    // beta = softmax(S) * mask -> d_out + hi/lo
    softmax_mask_split_kernel<<<MROWS, 256>>>(Sf, masks, beta_out, bh, bl);

    // O1[b] = beta_b @ V_b -> hi/lo   (B operand = Vt [CH, NTOK])
    mma_gemm<1><<<dim3(CH/128, HW/128, BATCH), T, SMEM_BYTES>>>(
        bh, bl, Vth, Vtl, nullptr, nullptr, O1h, O1l, NTOK, CH,
        (size_t)HW*NTOK, (size_t)CH*NTOK, (size_t)HW*CH);

    // o = O1 @ Wo + bo -> fp32 out
    mma_gemm<0><<<dim3(CH/128, MROWS/128, 1), T, SMEM_BYTES>>>(
        O1h, O1l, woh, wol, bo, o_out, nullptr, nullptr, CH, CH, 0, 0, 0);
}

// round 9
// speedup vs baseline: 1.8610x; 1.2209x over previous
#include <cuda_runtime.h>
#include <cuda_bf16.h>
#include <cstdint>
#include <cstddef>

#define BATCH 64
#define HW    256
#define CH    1024
#define NTOK  256
#define TC    768
#define FD    512
#define MROWS (BATCH*HW)   // 16384

// ------------------------------ scratch (device globals; no allocs) ---------
__device__ __align__(256) __nv_bfloat16 g_x1h[(size_t)MROWS*CH], g_x1l[(size_t)MROWS*CH];
__device__ __align__(256) __nv_bfloat16 g_x2h[(size_t)MROWS*TC], g_x2l[(size_t)MROWS*TC];
__device__ __align__(256) __nv_bfloat16 g_wqh[(size_t)FD*CH],  g_wql[(size_t)FD*CH];
__device__ __align__(256) __nv_bfloat16 g_wkh[(size_t)FD*TC],  g_wkl[(size_t)FD*TC];
__device__ __align__(256) __nv_bfloat16 g_wvh[(size_t)TC*CH],  g_wvl[(size_t)TC*CH];   // straight split of Wv [768,1024]
__device__ __align__(256) __nv_bfloat16 g_woh[(size_t)CH*CH],  g_wol[(size_t)CH*CH];   // Wo^T [f,c]
__device__ __align__(256) __nv_bfloat16 g_Qh[(size_t)MROWS*FD], g_Ql[(size_t)MROWS*FD];
__device__ __align__(256) __nv_bfloat16 g_Kh[(size_t)MROWS*FD], g_Kl[(size_t)MROWS*FD];
__device__ __align__(256) float         g_Wvo[(size_t)TC*CH];                          // Wv@Wo fp32
__device__ __align__(256) float         g_bvo[CH];                                     // bv@Wo
__device__ __align__(256) __nv_bfloat16 g_Wvoth[(size_t)CH*TC], g_Wvotl[(size_t)CH*TC];// (Wv@Wo)^T hi/lo
__device__ __align__(256) float         g_VW[(size_t)MROWS*CH];                        // x2@Wvo fp32
__device__ __align__(256) __nv_bfloat16 g_VWth[(size_t)MROWS*CH], g_VWtl[(size_t)MROWS*CH]; // [b][CH][NTOK]
__device__ __align__(256) float         g_S [(size_t)MROWS*NTOK];
__device__ __align__(256) __nv_bfloat16 g_bh[(size_t)MROWS*NTOK], g_bl[(size_t)MROWS*NTOK];

// ------------------------------ PTX helpers (all portable, sm_80+) ----------
__device__ __forceinline__ uint32_t smem_u32(const void* p) {
    uint32_t a;
    asm("{ .reg .u64 t; cvta.to.shared.u64 t, %1; cvt.u32.u64 %0, t; }" : "=r"(a) : "l"(p));
    return a;
}
#define CP_ASYNC16(dst, src) \
    asm volatile("cp.async.cg.shared.global [%0], [%1], 16;" :: "r"(dst), "l"(src))
#define CP_COMMIT() asm volatile("cp.async.commit_group;" ::: "memory")
#define CP_WAIT1()  asm volatile("cp.async.wait_group 1;" ::: "memory")
#define CP_WAIT0()  asm volatile("cp.async.wait_group 0;" ::: "memory")

#define LDMX4(r, addr)                                                      \
    asm volatile("ldmatrix.sync.aligned.m8n8.x4.shared.b16 {%0,%1,%2,%3}, [%4];" \
        : "=r"((r)[0]), "=r"((r)[1]), "=r"((r)[2]), "=r"((r)[3]) : "r"(addr))

#define MMA16816(c, a, b)                                                   \
    asm volatile("mma.sync.aligned.m16n8k16.row.col.f32.bf16.bf16.f32 "     \
        "{%0,%1,%2,%3}, {%4,%5,%6,%7}, {%8,%9}, {%0,%1,%2,%3};"             \
        : "+f"((c)[0]), "+f"((c)[1]), "+f"((c)[2]), "+f"((c)[3])            \
        : "r"((a)[0]), "r"((a)[1]), "r"((a)[2]), "r"((a)[3]),               \
          "r"((b)[0]), "r"((b)[1]))

// ------------------------------ GEMM (R7 config, unchanged) -----------------
// C[M,N] (+bias) = (Ah+Al)[M,K] * (Bh+Bl)[N,K]^T via 3 bf16 MMAs (AhBh+AhBl+AlBh).
// CTA tile 128x128, K-slab 32, 8 warps, cp.async double buffer, 64KB smem
// => 2 CTAs/SM. SMEM rows: chunks 0-3 hi, 4-7 lo, XOR swizzle.
// Requires M,N % 128 == 0, K % 32 == 0.
// MODE 0: fp32 C.  MODE 1: bf16 hi/lo split C.

#define STG_BYTES 32768
#define SMEM_BYTES (2*STG_BYTES)

__device__ __forceinline__ void cp_tile2(
    const __nv_bfloat16* __restrict__ gh, const __nv_bfloat16* __restrict__ gl,
    int row0, int kof, int pitch, uint32_t sdst, int tid)
{
#pragma unroll
    for (int i = 0; i < 2; ++i) {
        int u = tid + i * 256;
        int row = u >> 2;
        int c4 = u & 3;
        {
            int c = c4;
            uint32_t dst = sdst + row * 128 + ((c ^ (row & 7)) << 4);
            const void* src = gh + (size_t)(row0 + row) * pitch + kof + c4 * 8;
            CP_ASYNC16(dst, src);
        }
        {
            int c = c4 + 4;
            uint32_t dst = sdst + row * 128 + ((c ^ (row & 7)) << 4);
            const void* src = gl + (size_t)(row0 + row) * pitch + kof + c4 * 8;
            CP_ASYNC16(dst, src);
        }
    }
}

template <int MODE>
__global__ __launch_bounds__(256, 2) void mma_gemm(
    const __nv_bfloat16* __restrict__ Ah, const __nv_bfloat16* __restrict__ Al,
    const __nv_bfloat16* __restrict__ Bh, const __nv_bfloat16* __restrict__ Bl,
    const float* __restrict__ bias,
    float* __restrict__ Cf, __nv_bfloat16* __restrict__ Chi, __nv_bfloat16* __restrict__ Clo,
    int K, int ldc, size_t sA, size_t sB, size_t sC)
{
    extern __shared__ char smem[];
    const uint32_t sbase = smem_u32(smem);
    const int tid  = threadIdx.x;
    const int lane = tid & 31;
    const int wid  = tid >> 5;
    const int mw   = wid & 3;
    const int nw   = wid >> 2;
    const int m0 = blockIdx.y * 128;
    const int n0 = blockIdx.x * 128;
    const size_t z = blockIdx.z;
    Ah += z * sA; Al += z * sA;
    Bh += z * sB; Bl += z * sB;

    float c[2][8][4];
#pragma unroll
    for (int i = 0; i < 2; ++i)
#pragma unroll
        for (int j = 0; j < 8; ++j)
#pragma unroll
            for (int e = 0; e < 4; ++e) c[i][j][e] = 0.f;

    const int KS = K >> 5;

    cp_tile2(Ah, Al, m0, 0, K, sbase + 0,     tid);
    cp_tile2(Bh, Bl, n0, 0, K, sbase + 16384, tid);
    CP_COMMIT();

    const int a_r = lane & 15;
    const int a_c = lane >> 4;
    const int b_r = ((lane >> 4) << 3) + (lane & 7);
    const int b_c = (lane >> 3) & 1;

    for (int s = 0; s < KS; ++s) {
        const uint32_t sb = sbase + (s & 1) * STG_BYTES;
        if (s + 1 < KS) {
            const uint32_t nb = sbase + ((s + 1) & 1) * STG_BYTES;
            const int kof = (s + 1) * 32;
            cp_tile2(Ah, Al, m0, kof, K, nb + 0,     tid);
            cp_tile2(Bh, Bl, n0, kof, K, nb + 16384, tid);
            CP_COMMIT();
            CP_WAIT1();
        } else {
            CP_WAIT0();
        }
        __syncthreads();

#pragma unroll
        for (int kk = 0; kk < 2; ++kk) {
            uint32_t a_h[2][4], a_l[2][4];
#pragma unroll
            for (int mi = 0; mi < 2; ++mi) {
                const int row = mw * 32 + mi * 16 + a_r;
                const int ch = kk * 2 + a_c;
                const uint32_t base = sb + row * 128;
                LDMX4(a_h[mi], base + ((ch       ^ (row & 7)) << 4));
                LDMX4(a_l[mi], base + (((ch + 4) ^ (row & 7)) << 4));
            }
#pragma unroll
            for (int np = 0; np < 4; ++np) {
                const int n = nw * 64 + np * 16 + b_r;
                const int ch = kk * 2 + b_c;
                const uint32_t base = sb + 16384 + n * 128;
                uint32_t bhf[4], blf[4];
                LDMX4(bhf, base + ((ch       ^ (n & 7)) << 4));
                LDMX4(blf, base + (((ch + 4) ^ (n & 7)) << 4));
#pragma unroll
                for (int mi = 0; mi < 2; ++mi) {
                    MMA16816(c[mi][2*np+0], a_h[mi], &bhf[0]);
                    MMA16816(c[mi][2*np+0], a_h[mi], &blf[0]);
                    MMA16816(c[mi][2*np+0], a_l[mi], &bhf[0]);
                    MMA16816(c[mi][2*np+1], a_h[mi], &bhf[2]);
                    MMA16816(c[mi][2*np+1], a_h[mi], &blf[2]);
                    MMA16816(c[mi][2*np+1], a_l[mi], &bhf[2]);
                }
            }
        }
        __syncthreads();
    }

    const int r_base = m0 + mw * 32 + (lane >> 2);
    const int c_base = n0 + nw * 64 + (lane & 3) * 2;
#pragma unroll
    for (int mi = 0; mi < 2; ++mi) {
#pragma unroll
        for (int hf = 0; hf < 2; ++hf) {
            const size_t row = (size_t)(r_base + mi * 16 + hf * 8);
#pragma unroll
            for (int nj = 0; nj < 8; ++nj) {
                const int col = c_base + nj * 8;
                float v0 = c[mi][nj][hf * 2 + 0];
                float v1 = c[mi][nj][hf * 2 + 1];
                if (bias) { v0 += __ldg(&bias[col]); v1 += __ldg(&bias[col + 1]); }
                if (MODE == 0) {
                    float2* dst = (float2*)(Cf + z * sC + row * ldc + col);
                    *dst = make_float2(v0, v1);
                } else {
                    __nv_bfloat16 h0 = __float2bfloat16_rn(v0);
                    __nv_bfloat16 h1 = __float2bfloat16_rn(v1);
                    __nv_bfloat16 l0 = __float2bfloat16_rn(v0 - __bfloat162float(h0));
                    __nv_bfloat16 l1 = __float2bfloat16_rn(v1 - __bfloat162float(h1));
                    uint32_t hw = (uint32_t)__bfloat16_as_ushort(h0) | ((uint32_t)__bfloat16_as_ushort(h1) << 16);
                    uint32_t lw = (uint32_t)__bfloat16_as_ushort(l0) | ((uint32_t)__bfloat16_as_ushort(l1) << 16);
                    *(uint32_t*)(Chi + z * sC + row * ldc + col) = hw;
                    *(uint32_t*)(Clo + z * sC + row * ldc + col) = lw;
                }
            }
        }
    }
}

// ------------------------------ aux kernels ---------------------------------
__global__ __launch_bounds__(256) void split_kernel(
    const float4* __restrict__ src, __nv_bfloat16* __restrict__ dh,
    __nv_bfloat16* __restrict__ dl, int n4)
{
    int i = blockIdx.x * 256 + threadIdx.x;
    if (i >= n4) return;
    float4 v = src[i];
    float fv[4] = {v.x, v.y, v.z, v.w};
    uint32_t hw[2], lw[2];
#pragma unroll
    for (int p = 0; p < 2; ++p) {
        __nv_bfloat16 h0 = __float2bfloat16_rn(fv[2*p]);
        __nv_bfloat16 h1 = __float2bfloat16_rn(fv[2*p+1]);
        __nv_bfloat16 l0 = __float2bfloat16_rn(fv[2*p]   - __bfloat162float(h0));
        __nv_bfloat16 l1 = __float2bfloat16_rn(fv[2*p+1] - __bfloat162float(h1));
        hw[p] = (uint32_t)__bfloat16_as_ushort(h0) | ((uint32_t)__bfloat16_as_ushort(h1) << 16);
        lw[p] = (uint32_t)__bfloat16_as_ushort(l0) | ((uint32_t)__bfloat16_as_ushort(l1) << 16);
    }
    ((uint2*)dh)[i] = make_uint2(hw[0], hw[1]);
    ((uint2*)dl)[i] = make_uint2(lw[0], lw[1]);
}

// dst[c][r] = split(src[r][c]); src [R,C] fp32, dst [C,R] bf16 hi/lo, batched.
__global__ __launch_bounds__(256) void tsplit_kernel(
    const float* __restrict__ src, __nv_bfloat16* __restrict__ dh,
    __nv_bfloat16* __restrict__ dl, int R, int C, size_t sS, size_t sD)
{
    __shared__ float t[32][33];
    const size_t z = blockIdx.z;
    src += z * sS; dh += z * sD; dl += z * sD;
    const int c0 = blockIdx.x * 32, r0 = blockIdx.y * 32;
    const int tx = threadIdx.x, ty = threadIdx.y;
#pragma unroll
    for (int k = 0; k < 4; ++k)
        t[ty + 8*k][tx] = src[(size_t)(r0 + ty + 8*k) * C + c0 + tx];
    __syncthreads();
#pragma unroll
    for (int k = 0; k < 4; ++k) {
        float f = t[tx][ty + 8*k];
        __nv_bfloat16 h = __float2bfloat16_rn(f);
        size_t o = (size_t)(c0 + ty + 8*k) * R + r0 + tx;
        dh[o] = h;
        dl[o] = __float2bfloat16_rn(f - __bfloat162float(h));
    }
}

// bvo[f] = sum_c bv[c] * Wo[c][f]
__global__ __launch_bounds__(256) void bvo_kernel(
    const float* __restrict__ bv, const float* __restrict__ wo,
    float* __restrict__ bvo)
{
    int f = blockIdx.x * 256 + threadIdx.x;
    float s = 0.f;
    for (int c = 0; c < CH; ++c) s = fmaf(bv[c], wo[(size_t)c * CH + f], s);
    bvo[f] = s;
}

__global__ __launch_bounds__(256) void softmax_mask_split_kernel(
    const float* __restrict__ S, const float* __restrict__ masks,
    float* __restrict__ beta, __nv_bfloat16* __restrict__ bh,
    __nv_bfloat16* __restrict__ bl)
{
    const int row = blockIdx.x;
    const int b = row >> 8;
    const int n = threadIdx.x;
    __shared__ float red[256];

    const size_t idx = (size_t)row * NTOK + n;
    float v = S[idx];
    red[n] = v;
    __syncthreads();
#pragma unroll
    for (int s = 128; s > 0; s >>= 1) {
        if (n < s) red[n] = fmaxf(red[n], red[n + s]);
        __syncthreads();
    }
    const float mx = red[0];
    __syncthreads();
    const float e = expf(v - mx);
    red[n] = e;
    __syncthreads();
#pragma unroll
    for (int s = 128; s > 0; s >>= 1) {
        if (n < s) red[n] += red[n + s];
        __syncthreads();
    }
    const float r = e / red[0] * masks[b * NTOK + n];
    beta[idx] = r;
    __nv_bfloat16 h = __float2bfloat16_rn(r);
    bh[idx] = h;
    bl[idx] = __float2bfloat16_rn(r - __bfloat162float(h));
}

// ------------------------------ host ----------------------------------------
extern "C" void kernel_launch(void* const* d_in, const int* in_sizes, int n_in,
                              void* d_out, int out_size) {
    const float* x1    = (const float*)d_in[0];
    const float* x2    = (const float*)d_in[1];
    const float* masks = (const float*)d_in[2];
    const float* wq    = (const float*)d_in[3];
    const float* bq    = (const float*)d_in[4];
    const float* wk    = (const float*)d_in[5];
    const float* bk    = (const float*)d_in[6];
    const float* wv    = (const float*)d_in[7];
    const float* bv    = (const float*)d_in[8];
    const float* wo    = (const float*)d_in[9];
    const float* bo    = (const float*)d_in[10];

    float* out      = (float*)d_out;
    float* o_out    = out;
    float* beta_out = out + (size_t)MROWS * CH;

    __nv_bfloat16 *x1h, *x1l, *x2h, *x2l, *wqh, *wql, *wkh, *wkl, *wvh, *wvl,
                  *woh, *wol, *Qh, *Ql, *Kh, *Kl, *Wvoth, *Wvotl, *VWth, *VWtl, *bh, *bl;
    float *Wvo, *bvo, *VWf, *Sf;
    cudaGetSymbolAddress((void**)&x1h, g_x1h); cudaGetSymbolAddress((void**)&x1l, g_x1l);
    cudaGetSymbolAddress((void**)&x2h, g_x2h); cudaGetSymbolAddress((void**)&x2l, g_x2l);
    cudaGetSymbolAddress((void**)&wqh, g_wqh); cudaGetSymbolAddress((void**)&wql, g_wql);
    cudaGetSymbolAddress((void**)&wkh, g_wkh); cudaGetSymbolAddress((void**)&wkl, g_wkl);
    cudaGetSymbolAddress((void**)&wvh, g_wvh); cudaGetSymbolAddress((void**)&wvl, g_wvl);
    cudaGetSymbolAddress((void**)&woh, g_woh); cudaGetSymbolAddress((void**)&wol, g_wol);
    cudaGetSymbolAddress((void**)&Qh,  g_Qh);  cudaGetSymbolAddress((void**)&Ql,  g_Ql);
    cudaGetSymbolAddress((void**)&Kh,  g_Kh);  cudaGetSymbolAddress((void**)&Kl,  g_Kl);
    cudaGetSymbolAddress((void**)&Wvo, g_Wvo); cudaGetSymbolAddress((void**)&bvo, g_bvo);
    cudaGetSymbolAddress((void**)&Wvoth, g_Wvoth); cudaGetSymbolAddress((void**)&Wvotl, g_Wvotl);
    cudaGetSymbolAddress((void**)&VWf, g_VW);
    cudaGetSymbolAddress((void**)&VWth, g_VWth); cudaGetSymbolAddress((void**)&VWtl, g_VWtl);
    cudaGetSymbolAddress((void**)&Sf,  g_S);
    cudaGetSymbolAddress((void**)&bh,  g_bh);  cudaGetSymbolAddress((void**)&bl,  g_bl);

    cudaFuncSetAttribute(mma_gemm<0>, cudaFuncAttributeMaxDynamicSharedMemorySize, SMEM_BYTES);
    cudaFuncSetAttribute(mma_gemm<1>, cudaFuncAttributeMaxDynamicSharedMemorySize, SMEM_BYTES);

    const dim3 T(256);
    const dim3 TT(32, 8);

    // splits
    split_kernel<<<(MROWS*CH/4 + 255)/256, 256>>>((const float4*)x1, x1h, x1l, MROWS*CH/4);
    split_kernel<<<(MROWS*TC/4 + 255)/256, 256>>>((const float4*)x2, x2h, x2l, MROWS*TC/4);
    split_kernel<<<(TC*CH/4 + 255)/256, 256>>>((const float4*)wv, wvh, wvl, TC*CH/4);  // Wv row-major [768,1024]
    tsplit_kernel<<<dim3(FD/32, CH/32, 1), TT>>>(wq, wqh, wql, CH, FD, 0, 0);          // Wq^T
    tsplit_kernel<<<dim3(FD/32, TC/32, 1), TT>>>(wk, wkh, wkl, TC, FD, 0, 0);          // Wk^T
    tsplit_kernel<<<dim3(CH/32, CH/32, 1), TT>>>(wo, woh, wol, CH, CH, 0, 0);          // Wo^T
    bvo_kernel<<<CH/256, 256>>>(bv, wo, bvo);

    // Wvo = Wv @ Wo   (M=768, N=1024, K=1024)
    mma_gemm<0><<<dim3(CH/128, TC/128, 1), T, SMEM_BYTES>>>(
        wvh, wvl, woh, wol, nullptr, Wvo, nullptr, nullptr, CH, CH, 0, 0, 0);
    // (Wv@Wo)^T hi/lo  [1024, 768]
    tsplit_kernel<<<dim3(CH/32, TC/32, 1), TT>>>(Wvo, Wvoth, Wvotl, TC, CH, 0, 0);

    // Q = x1 @ Wq + bq  -> hi/lo   (M=16384, N=512, K=1024)
    mma_gemm<1><<<dim3(FD/128, MROWS/128, 1), T, SMEM_BYTES>>>(
        x1h, x1l, wqh, wql, bq, nullptr, Qh, Ql, CH, FD, 0, 0, 0);
    // K = x2 @ Wk + bk  -> hi/lo   (M=16384, N=512, K=768)
    mma_gemm<1><<<dim3(FD/128, MROWS/128, 1), T, SMEM_BYTES>>>(
        x2h, x2l, wkh, wkl, bk, nullptr, Kh, Kl, TC, FD, 0, 0, 0);

    // VW = x2 @ Wvo + bvo  -> fp32   (M=16384, N=1024, K=768)
    mma_gemm<0><<<dim3(CH/128, MROWS/128, 1), T, SMEM_BYTES>>>(
        x2h, x2l, Wvoth, Wvotl, bvo, VWf, nullptr, nullptr, TC, CH, 0, 0, 0);
    // per-batch transpose+split: VWt[b][CH][NTOK]
    tsplit_kernel<<<dim3(CH/32, NTOK/32, BATCH), TT>>>(
        VWf, VWth, VWtl, NTOK, CH, (size_t)NTOK*CH, (size_t)NTOK*CH);

    // S[b] = Q_b @ K_b^T -> fp32   (per-batch 256x256, K=512)
    mma_gemm<0><<<dim3(NTOK/128, HW/128, BATCH), T, SMEM_BYTES>>>(
        Qh, Ql, Kh, Kl, nullptr, Sf, nullptr, nullptr, FD, NTOK,
        (size_t)HW*FD, (size_t)NTOK*FD, (size_t)HW*NTOK);

    // beta = softmax(S) * mask -> d_out + hi/lo
    softmax_mask_split_kernel<<<MROWS, 256>>>(Sf, masks, beta_out, bh, bl);

    // o[b] = beta_b @ VW_b + bo -> fp32 out   (per-batch 256x1024, K=256)
    mma_gemm<0><<<dim3(CH/128, HW/128, BATCH), T, SMEM_BYTES>>>(
        bh, bl, VWth, VWtl, bo, o_out, nullptr, nullptr, NTOK, CH,
        (size_t)HW*NTOK, (size_t)CH*NTOK, (size_t)HW*CH);
}